// round 11
// baseline (speedup 1.0000x reference)
#include <cuda_runtime.h>
#include <cstdint>

// FlexMoERouter: logits[8192,16] = x*Wg + image*Wi + text*Wt + audio*Wa + biases
// -> softmax -> top4 (renorm) -> aux loss.
// Output (float32): [0,32768) idx as float, [32768,65536) probs, [65536] aux.

#define B_    4
#define S_    2048
#define H_    1024
#define E_    16
#define TOPK  4
#define NTOK  (B_ * S_)        // 8192
#define TPB   64               // tokens per block
#define NBLK  (NTOK / TPB)     // 128 blocks (one wave, 1 CTA/SM)
#define KC    128              // k floats per stage
#define NSTG  32               // 4 modalities x 8 k-chunks
#define NBUF  4
#define RSTR  132              // smem row stride (floats): 33x16B (odd granule count)
#define RPB   (TPB + E_)       // rows per buffer: 64 x-rows + 16 W-rows
#define STG_BYTES (RPB * KC * 4)   // 80*512 = 40960

// dynamic smem (floats): 4 buffers of 80 rows x 132 floats
#define BUF(b)  ((b) * (RPB * RSTR))
#define SMEMF   (NBUF * RPB * RSTR)          // 42240 floats
#define SMEMB   (SMEMF * 4)                  // 168960 bytes

__device__ float g_Wt[4][E_][H_];       // transposed weights: g_Wt[m][e][k]
__device__ float g_partial[NBLK][E_];   // per-block sum of router_probs per expert
__device__ int   g_count;               // zero-init; self-resets each launch

__device__ __forceinline__ void fma2(unsigned long long& acc,
                                     unsigned long long a, unsigned long long b)
{
    asm("fma.rn.f32x2 %0, %1, %2, %0;" : "+l"(acc) : "l"(a), "l"(b));
}
__device__ __forceinline__ float fma2_lo(unsigned long long v) {
    return __uint_as_float((unsigned)(v & 0xffffffffull));
}
__device__ __forceinline__ float fma2_hi(unsigned long long v) {
    return __uint_as_float((unsigned)(v >> 32));
}

__device__ __forceinline__ void mbar_init(uint32_t mbar, uint32_t count) {
    asm volatile("mbarrier.init.shared.b64 [%0], %1;" :: "r"(mbar), "r"(count) : "memory");
}
__device__ __forceinline__ void mbar_expect_tx(uint32_t mbar, uint32_t tx) {
    asm volatile("mbarrier.arrive.expect_tx.shared.b64 _, [%0], %1;"
                 :: "r"(mbar), "r"(tx) : "memory");
}
__device__ __forceinline__ void mbar_wait(uint32_t mbar, uint32_t parity) {
    uint32_t done;
    asm volatile(
        "{\n\t.reg .pred p;\n\t"
        "mbarrier.try_wait.parity.acquire.cta.shared::cta.b64 p, [%1], %2;\n\t"
        "selp.b32 %0, 1, 0, p;\n\t}"
        : "=r"(done) : "r"(mbar), "r"(parity) : "memory");
    if (!done) {
        asm volatile(
            "{\n\t.reg .pred P1;\n\t"
            "WAIT_LOOP_%=:\n\t"
            "mbarrier.try_wait.parity.acquire.cta.shared::cta.b64 P1, [%0], %1, 0x989680;\n\t"
            "@P1 bra.uni WAIT_DONE_%=;\n\t"
            "bra.uni WAIT_LOOP_%=;\n\t"
            "WAIT_DONE_%=:\n\t}"
            :: "r"(mbar), "r"(parity) : "memory");
    }
}
__device__ __forceinline__ void bulk_cp(uint32_t dst, const float* src,
                                        uint32_t bytes, uint32_t mbar) {
    asm volatile(
        "cp.async.bulk.shared::cta.global.mbarrier::complete_tx::bytes [%0], [%1], %2, [%3];"
        :: "r"(dst), "l"(src), "r"(bytes), "r"(mbar) : "memory");
}

__device__ __forceinline__ float4 f4_add(float4 a, float4 b) {
    return make_float4(a.x + b.x, a.y + b.y, a.z + b.z, a.w + b.w);
}
__device__ __forceinline__ float4 f4_shfl_xor(float4 v, int m) {
    float4 r;
    r.x = __shfl_xor_sync(0xffffffffu, v.x, m);
    r.y = __shfl_xor_sync(0xffffffffu, v.y, m);
    r.z = __shfl_xor_sync(0xffffffffu, v.z, m);
    r.w = __shfl_xor_sync(0xffffffffu, v.w, m);
    return r;
}

// Pre-kernel: transpose W[1024][16] -> g_Wt[m][16][1024].
__global__ void transpose_W(const float* __restrict__ Wg, const float* __restrict__ Wi,
                            const float* __restrict__ Wt, const float* __restrict__ Wa)
{
    const float* Ws[4] = {Wg, Wi, Wt, Wa};
    const int idx = blockIdx.x * 256 + threadIdx.x;   // 0..16383
    const int m = idx >> 12;
    const int r = idx & 4095;
    const int k = r >> 2;
    const int ec = r & 3;
    float4 v = reinterpret_cast<const float4*>(Ws[m])[r];
    g_Wt[m][ec * 4 + 0][k] = v.x;
    g_Wt[m][ec * 4 + 1][k] = v.y;
    g_Wt[m][ec * 4 + 2][k] = v.z;
    g_Wt[m][ec * 4 + 3][k] = v.w;
}

__global__ __launch_bounds__(256, 1)
void router_main(const float* __restrict__ x,   const float* __restrict__ img,
                 const float* __restrict__ txt, const float* __restrict__ aud,
                 const float* __restrict__ bg,  const float* __restrict__ bi,
                 const float* __restrict__ bt,  const float* __restrict__ ba,
                 float* __restrict__ out)
{
    extern __shared__ float sm[];
    __shared__ uint64_t mbars[NBUF];
    __shared__ float  sl[TPB][E_];       // logits (bias included)
    __shared__ float  bsum[E_];
    __shared__ float  wpart[2][E_];
    __shared__ float4 red_smf[8][4];
    __shared__ float  red_sterm[4];
    __shared__ int    s_isLast;

    const int tid  = threadIdx.x;
    const int lane = tid & 31;
    const int warp = tid >> 5;             // 0..7  (k-granule class: g % 8 == warp)
    const int tokB0 = blockIdx.x * TPB;

    const float* xs_[4] = {x, img, txt, aud};
    const uint32_t smem_base = (uint32_t)__cvta_generic_to_shared(sm);
    const uint32_t mbar_base = (uint32_t)__cvta_generic_to_shared(&mbars[0]);

    if (tid < E_) bsum[tid] = bg[tid] + bi[tid] + bt[tid] + ba[tid];
    if (tid == 0) {
#pragma unroll
        for (int b = 0; b < NBUF; b++) mbar_init(mbar_base + b * 8, 1);
    }
    __syncthreads();

    // acc2[t][e]: token t = lane + 32*t, expert e; f32x2 over (even-k, odd-k)
    unsigned long long acc2[2][E_];
#pragma unroll
    for (int t = 0; t < 2; t++)
#pragma unroll
        for (int e = 0; e < E_; e++) acc2[t][e] = 0ull;

    // ---- bulk-copy stage issue (single elected thread): 64 x-rows + 16 W-rows ----
    auto issue = [&](int s) {
        const int m  = s >> 3;
        const int kc = (s & 7) * KC;
        const int b  = s & (NBUF - 1);
        const uint32_t mb = mbar_base + b * 8;
        const uint32_t bd = smem_base + BUF(b) * 4;
        mbar_expect_tx(mb, STG_BYTES);
        const float* xsrc = xs_[m] + (size_t)tokB0 * H_ + kc;
#pragma unroll 4
        for (int r = 0; r < TPB; r++)
            bulk_cp(bd + (uint32_t)(r * RSTR) * 4, xsrc + (size_t)r * H_, KC * 4, mb);
        const float* wsrc = &g_Wt[m][0][kc];
#pragma unroll 4
        for (int r = 0; r < E_; r++)
            bulk_cp(bd + (uint32_t)((TPB + r) * RSTR) * 4, wsrc + (size_t)r * H_, KC * 4, mb);
    };

    if (tid == 0) { issue(0); issue(1); issue(2); }

#pragma unroll 1
    for (int s = 0; s < NSTG; s++) {
        const int b = s & (NBUF - 1);
        mbar_wait(mbar_base + b * 8, (s >> 2) & 1);

        const float* xb = sm + BUF(b);
        const float* wb = xb + TPB * RSTR;
        const ulonglong2* xr0 = reinterpret_cast<const ulonglong2*>(xb + lane * RSTR);
        const ulonglong2* xr1 = reinterpret_cast<const ulonglong2*>(xb + (lane + 32) * RSTR);

#pragma unroll
        for (int i = 0; i < 4; i++) {
            const int o = warp + 8 * i;            // this warp's granule in stage
            const ulonglong2 xv0 = xr0[o];
            const ulonglong2 xv1 = xr1[o];
#pragma unroll
            for (int e = 0; e < E_; e++) {
                const ulonglong2 wv =
                    reinterpret_cast<const ulonglong2*>(wb + e * RSTR)[o];  // warp-uniform
                fma2(acc2[0][e], xv0.x, wv.x);
                fma2(acc2[0][e], xv0.y, wv.y);
                fma2(acc2[1][e], xv1.x, wv.x);
                fma2(acc2[1][e], xv1.y, wv.y);
            }
        }
        __syncthreads();                  // all consumed stage s => buf (s+3)%4 is free
        if (tid == 0 && s + 3 < NSTG) issue(s + 3);
    }

    // ---- cross-warp (k) reduction via smem: red[w][tok][e] over buffer region ----
    float* red = sm;                       // 8*64*16 floats = 32KB (buffers done)
#pragma unroll
    for (int t = 0; t < 2; t++) {
        const int row = lane + 32 * t;
        float4* dst = reinterpret_cast<float4*>(red + warp * (TPB * E_) + row * E_);
#pragma unroll
        for (int q = 0; q < 4; q++) {
            dst[q] = make_float4(
                fma2_lo(acc2[t][q * 4 + 0]) + fma2_hi(acc2[t][q * 4 + 0]),
                fma2_lo(acc2[t][q * 4 + 1]) + fma2_hi(acc2[t][q * 4 + 1]),
                fma2_lo(acc2[t][q * 4 + 2]) + fma2_hi(acc2[t][q * 4 + 2]),
                fma2_lo(acc2[t][q * 4 + 3]) + fma2_hi(acc2[t][q * 4 + 3]));
        }
    }
    __syncthreads();

    {   // 256 threads: each sums 8 warp-partials for (token, expert-quad)
        const int t = tid >> 2;
        const int q = tid & 3;
        float4 s4 = make_float4(0.f, 0.f, 0.f, 0.f);
#pragma unroll
        for (int w = 0; w < 8; w++)
            s4 = f4_add(s4, reinterpret_cast<const float4*>(
                                red + w * (TPB * E_) + t * E_ + q * 4)[0]);
        const float4 bq = reinterpret_cast<const float4*>(bsum)[q];
        reinterpret_cast<float4*>(&sl[t][q * 4])[0] = f4_add(s4, bq);
    }
    __syncthreads();

    // ---- epilogue: threads 0..63, one token each ----
    if (tid < TPB) {
        const int g = blockIdx.x * TPB + tid;
        float p[E_], q[E_];
        float mx = -1e30f;
#pragma unroll
        for (int e = 0; e < E_; e++) {
            float l = sl[tid][e];
            p[e] = l;
            mx = fmaxf(mx, l);
        }
        float ssum = 0.0f;
#pragma unroll
        for (int e = 0; e < E_; e++) { p[e] = expf(p[e] - mx); ssum += p[e]; }
        const float inv = 1.0f / ssum;
#pragma unroll
        for (int e = 0; e < E_; e++) { p[e] *= inv; q[e] = p[e]; }

        float tp[TOPK]; int ti[TOPK]; float tsum = 0.0f;
#pragma unroll
        for (int j = 0; j < TOPK; j++) {
            float best = -1.0f; int bidx = 0;
#pragma unroll
            for (int e = 0; e < E_; e++)
                if (p[e] > best) { best = p[e]; bidx = e; }
            tp[j] = best; ti[j] = bidx; tsum += best;
            p[bidx] = -2.0f;
        }
        const float tinv = 1.0f / tsum;
        float4* oi = reinterpret_cast<float4*>(out + (size_t)g * TOPK);
        float4* op = reinterpret_cast<float4*>(out + (size_t)NTOK * TOPK + (size_t)g * TOPK);
        *oi = make_float4((float)ti[0], (float)ti[1], (float)ti[2], (float)ti[3]);
        *op = make_float4(tp[0] * tinv, tp[1] * tinv, tp[2] * tinv, tp[3] * tinv);

        // per-expert prob sums, warp-local (warp 0: tokens 0-31, warp 1: 32-63)
#pragma unroll
        for (int e = 0; e < E_; e++) {
            float v = q[e];
            v += __shfl_xor_sync(0xffffffffu, v, 16);
            v += __shfl_xor_sync(0xffffffffu, v, 8);
            v += __shfl_xor_sync(0xffffffffu, v, 4);
            v += __shfl_xor_sync(0xffffffffu, v, 2);
            v += __shfl_xor_sync(0xffffffffu, v, 1);
            if (lane == 0) wpart[warp][e] = v;
        }
    }
    __syncthreads();
    if (tid < E_)
        g_partial[blockIdx.x][tid] = wpart[0][tid] + wpart[1][tid];
    __syncthreads();

    // ---- last block reduces g_partial -> aux loss (fixed order, deterministic) ----
    if (tid == 0) {
        __threadfence();
        int old = atomicAdd(&g_count, 1);
        s_isLast = (old == NBLK - 1);
    }
    __syncthreads();
    if (s_isLast) {
        __threadfence();
        // g_partial = 128 x 16 = 512 float4
        const float4* gp4 = reinterpret_cast<const float4*>(&g_partial[0][0]);
        float4 v = f4_add(gp4[tid], gp4[tid + 256]);
        v = f4_add(v, f4_shfl_xor(v, 4));
        v = f4_add(v, f4_shfl_xor(v, 8));
        v = f4_add(v, f4_shfl_xor(v, 16));
        if (lane < 4) red_smf[warp][lane] = v;
        __syncthreads();
        if (tid < 4) {
            float4 t = red_smf[0][tid];
#pragma unroll
            for (int w = 1; w < 8; w++) t = f4_add(t, red_smf[w][tid]);
            const float invn = 1.0f / (float)NTOK;
            float s = 0.0f, pe;
            pe = t.x * invn; s += pe * logf(pe * (float)E_ + 1e-9f);
            pe = t.y * invn; s += pe * logf(pe * (float)E_ + 1e-9f);
            pe = t.z * invn; s += pe * logf(pe * (float)E_ + 1e-9f);
            pe = t.w * invn; s += pe * logf(pe * (float)E_ + 1e-9f);
            red_sterm[tid] = s;
        }
        __syncthreads();
        if (tid == 0) {
            out[(size_t)NTOK * TOPK * 2] = red_sterm[0] + red_sterm[1]
                                         + red_sterm[2] + red_sterm[3];
            g_count = 0;                 // reset for next graph replay
        }
    }
}

extern "C" void kernel_launch(void* const* d_in, const int* in_sizes, int n_in,
                              void* d_out, int out_size)
{
    (void)in_sizes; (void)n_in; (void)out_size;
    const float* x   = (const float*)d_in[0];
    const float* img = (const float*)d_in[1];
    const float* txt = (const float*)d_in[2];
    const float* aud = (const float*)d_in[3];
    const float* Wg  = (const float*)d_in[4];
    const float* bg  = (const float*)d_in[5];
    const float* Wi  = (const float*)d_in[6];
    const float* bi  = (const float*)d_in[7];
    const float* Wt  = (const float*)d_in[8];
    const float* bt  = (const float*)d_in[9];
    const float* Wa  = (const float*)d_in[10];
    const float* ba  = (const float*)d_in[11];
    float* out = (float*)d_out;

    cudaFuncSetAttribute(router_main, cudaFuncAttributeMaxDynamicSharedMemorySize, SMEMB);

    transpose_W<<<64, 256>>>(Wg, Wi, Wt, Wa);
    router_main<<<NBLK, 256, SMEMB>>>(x, img, txt, aud, bg, bi, bt, ba, out);
}

// round 12
// speedup vs baseline: 2.7858x; 2.7858x over previous
#include <cuda_runtime.h>
#include <cstdint>

// FlexMoERouter: logits[8192,16] = x*Wg + image*Wi + text*Wt + audio*Wa + biases
// -> softmax -> top4 (renorm) -> aux loss.
// Output (float32): [0,32768) idx as float, [32768,65536) probs, [65536] aux.

#define B_    4
#define S_    2048
#define H_    1024
#define E_    16
#define TOPK  4
#define NTOK  (B_ * S_)        // 8192
#define TPB   64               // tokens per block
#define NTHR  512
#define NBLK  (NTOK / TPB)     // 128 blocks (one per SM, balanced)
#define KC    128              // k floats per stage
#define NSTG  32               // 4 modalities x 8 k-chunks
#define NBUF  3
#define RSTR  132              // smem row stride (floats): 33x16B granules (odd)
#define RPB   (TPB + E_)       // 80 rows per buffer (64 x + 16 W)

#define BUF(b)  ((b) * (RPB * RSTR))
#define SMEMF   (NBUF * RPB * RSTR)          // 31680 floats
#define SMEMB   (SMEMF * 4)                  // 126720 bytes

__device__ float g_Wt[4][E_][H_];       // transposed weights: g_Wt[m][e][k]
__device__ float g_partial[NBLK][E_];   // per-block sum of router_probs per expert
__device__ int   g_count;               // zero-init; self-resets each launch

__device__ __forceinline__ void fma2(unsigned long long& acc,
                                     unsigned long long a, unsigned long long b)
{
    asm("fma.rn.f32x2 %0, %1, %2, %0;" : "+l"(acc) : "l"(a), "l"(b));
}
__device__ __forceinline__ float fma2_lo(unsigned long long v) {
    return __uint_as_float((unsigned)(v & 0xffffffffull));
}
__device__ __forceinline__ float fma2_hi(unsigned long long v) {
    return __uint_as_float((unsigned)(v >> 32));
}
__device__ __forceinline__ void cp16(uint32_t dst_s, const float* src)
{
    asm volatile("cp.async.cg.shared.global [%0], [%1], 16;" :: "r"(dst_s), "l"(src));
}
__device__ __forceinline__ void cp_commit() { asm volatile("cp.async.commit_group;"); }
__device__ __forceinline__ void cp_wait1()  { asm volatile("cp.async.wait_group 1;"); }
__device__ __forceinline__ void cp_wait0()  { asm volatile("cp.async.wait_group 0;"); }

__device__ __forceinline__ float4 f4_add(float4 a, float4 b) {
    return make_float4(a.x + b.x, a.y + b.y, a.z + b.z, a.w + b.w);
}
__device__ __forceinline__ float4 f4_shfl_xor(float4 v, int m) {
    float4 r;
    r.x = __shfl_xor_sync(0xffffffffu, v.x, m);
    r.y = __shfl_xor_sync(0xffffffffu, v.y, m);
    r.z = __shfl_xor_sync(0xffffffffu, v.z, m);
    r.w = __shfl_xor_sync(0xffffffffu, v.w, m);
    return r;
}

// Pre-kernel: transpose W[1024][16] -> g_Wt[m][16][1024].
__global__ void transpose_W(const float* __restrict__ Wg, const float* __restrict__ Wi,
                            const float* __restrict__ Wt, const float* __restrict__ Wa)
{
    const float* Ws[4] = {Wg, Wi, Wt, Wa};
    const int idx = blockIdx.x * 256 + threadIdx.x;   // 0..16383
    const int m = idx >> 12;
    const int r = idx & 4095;
    const int k = r >> 2;
    const int ec = r & 3;
    float4 v = reinterpret_cast<const float4*>(Ws[m])[r];
    g_Wt[m][ec * 4 + 0][k] = v.x;
    g_Wt[m][ec * 4 + 1][k] = v.y;
    g_Wt[m][ec * 4 + 2][k] = v.z;
    g_Wt[m][ec * 4 + 3][k] = v.w;
}

__global__ __launch_bounds__(NTHR, 1)
void router_main(const float* __restrict__ x,   const float* __restrict__ img,
                 const float* __restrict__ txt, const float* __restrict__ aud,
                 const float* __restrict__ bg,  const float* __restrict__ bi,
                 const float* __restrict__ bt,  const float* __restrict__ ba,
                 float* __restrict__ out)
{
    extern __shared__ float sm[];
    __shared__ float  sl[TPB][E_];       // logits (bias included)
    __shared__ float  bsum[E_];
    __shared__ float  wpart[2][E_];
    __shared__ float4 red_smf[8][4];
    __shared__ float  red_sterm[4];
    __shared__ int    s_isLast;

    const int tid  = threadIdx.x;
    const int lane = tid & 31;
    const int warp = tid >> 5;             // 0..15
    const int gi   = warp >> 3;            // token half (0: tokens 0-31, 1: 32-63)
    const int wk   = warp & 7;             // k-granule class (g % 8 == wk)
    const int tokL = gi * 32 + lane;       // this thread's block-local token
    const int tokB0 = blockIdx.x * TPB;

    const float* xs_[4] = {x, img, txt, aud};
    const uint32_t smem_base = (uint32_t)__cvta_generic_to_shared(sm);

    if (tid < E_) bsum[tid] = bg[tid] + bi[tid] + bt[tid] + ba[tid];

    // acc2[e]: f32x2 partial (even-k, odd-k) for token tokL, expert e
    unsigned long long acc2[E_];
#pragma unroll
    for (int e = 0; e < E_; e++) acc2[e] = 0ull;

    // ---- async stage issue: x 64 rows x 128k (32KB) + W 16 rows x 128k (8KB) ----
    auto issue = [&](int s) {
        const int m  = s >> 3;
        const int kc = (s & 7) * KC;
        const int b  = s % NBUF;
        const uint32_t bd = smem_base + BUF(b) * 4;
        const float* xsrc = xs_[m] + (size_t)tokB0 * H_ + kc;
#pragma unroll
        for (int j = 0; j < 4; j++) {
            const int idx = tid + NTHR * j;        // 0..2047
            const int row = idx >> 5;
            const int g   = idx & 31;
            cp16(bd + (uint32_t)(row * RSTR + g * 4) * 4, xsrc + row * H_ + g * 4);
        }
        {
            const float* wsrc = &g_Wt[m][0][kc];
            const int row = tid >> 5;              // 0..15
            const int g   = tid & 31;
            cp16(bd + (uint32_t)((TPB + row) * RSTR + g * 4) * 4, wsrc + row * H_ + g * 4);
        }
        cp_commit();
    };

    issue(0);
    issue(1);
#pragma unroll 1
    for (int s = 0; s < NSTG; s++) {
        if (s == NSTG - 1) cp_wait0(); else cp_wait1();
        __syncthreads();                  // stage s visible; buf (s-1)%3 drained by all
        if (s + 2 < NSTG) issue(s + 2);

        const int b = s % NBUF;
        const float* xb = sm + BUF(b);
        const float* wb = xb + TPB * RSTR;
        const ulonglong2* xr = reinterpret_cast<const ulonglong2*>(xb + tokL * RSTR);

#pragma unroll
        for (int i = 0; i < 4; i++) {
            const int o = wk + 8 * i;              // this warp's granule in stage
            const ulonglong2 xv = xr[o];
#pragma unroll
            for (int e = 0; e < E_; e++) {
                const ulonglong2 wv =
                    reinterpret_cast<const ulonglong2*>(wb + e * RSTR)[o];  // warp-uniform
                fma2(acc2[e], xv.x, wv.x);
                fma2(acc2[e], xv.y, wv.y);
            }
        }
    }
    __syncthreads();                       // all compute done; stage bufs reusable

    // ---- cross-warp (k) reduction via smem: red[wk][tok][e] over buffer region ----
    float* red = sm;                       // 8*64*16 floats = 32KB
    {
        float4* dst = reinterpret_cast<float4*>(red + wk * (TPB * E_) + tokL * E_);
#pragma unroll
        for (int q = 0; q < 4; q++) {
            dst[q] = make_float4(
                fma2_lo(acc2[q * 4 + 0]) + fma2_hi(acc2[q * 4 + 0]),
                fma2_lo(acc2[q * 4 + 1]) + fma2_hi(acc2[q * 4 + 1]),
                fma2_lo(acc2[q * 4 + 2]) + fma2_hi(acc2[q * 4 + 2]),
                fma2_lo(acc2[q * 4 + 3]) + fma2_hi(acc2[q * 4 + 3]));
        }
    }
    __syncthreads();

    if (tid < 256) {   // 256 threads: each sums 8 k-partials for (token, expert-quad)
        const int t = tid >> 2;
        const int q = tid & 3;
        float4 s4 = make_float4(0.f, 0.f, 0.f, 0.f);
#pragma unroll
        for (int w = 0; w < 8; w++)
            s4 = f4_add(s4, reinterpret_cast<const float4*>(
                                red + w * (TPB * E_) + t * E_ + q * 4)[0]);
        const float4 bq = reinterpret_cast<const float4*>(bsum)[q];
        reinterpret_cast<float4*>(&sl[t][q * 4])[0] = f4_add(s4, bq);
    }
    __syncthreads();

    // ---- epilogue: threads 0..63, one token each ----
    if (tid < TPB) {
        const int g = blockIdx.x * TPB + tid;
        float p[E_], q[E_];
        float mx = -1e30f;
#pragma unroll
        for (int e = 0; e < E_; e++) {
            float l = sl[tid][e];
            p[e] = l;
            mx = fmaxf(mx, l);
        }
        float ssum = 0.0f;
#pragma unroll
        for (int e = 0; e < E_; e++) { p[e] = expf(p[e] - mx); ssum += p[e]; }
        const float inv = 1.0f / ssum;
#pragma unroll
        for (int e = 0; e < E_; e++) { p[e] *= inv; q[e] = p[e]; }

        float tp[TOPK]; int ti[TOPK]; float tsum = 0.0f;
#pragma unroll
        for (int j = 0; j < TOPK; j++) {
            float best = -1.0f; int bidx = 0;
#pragma unroll
            for (int e = 0; e < E_; e++)
                if (p[e] > best) { best = p[e]; bidx = e; }
            tp[j] = best; ti[j] = bidx; tsum += best;
            p[bidx] = -2.0f;
        }
        const float tinv = 1.0f / tsum;
        float4* oi = reinterpret_cast<float4*>(out + (size_t)g * TOPK);
        float4* op = reinterpret_cast<float4*>(out + (size_t)NTOK * TOPK + (size_t)g * TOPK);
        *oi = make_float4((float)ti[0], (float)ti[1], (float)ti[2], (float)ti[3]);
        *op = make_float4(tp[0] * tinv, tp[1] * tinv, tp[2] * tinv, tp[3] * tinv);

        // per-expert prob sums, warp-local (warp 0: tokens 0-31, warp 1: 32-63)
#pragma unroll
        for (int e = 0; e < E_; e++) {
            float v = q[e];
            v += __shfl_xor_sync(0xffffffffu, v, 16);
            v += __shfl_xor_sync(0xffffffffu, v, 8);
            v += __shfl_xor_sync(0xffffffffu, v, 4);
            v += __shfl_xor_sync(0xffffffffu, v, 2);
            v += __shfl_xor_sync(0xffffffffu, v, 1);
            if (lane == 0) wpart[warp][e] = v;
        }
    }
    __syncthreads();
    if (tid < E_)
        g_partial[blockIdx.x][tid] = wpart[0][tid] + wpart[1][tid];
    __syncthreads();

    // ---- last block reduces g_partial -> aux loss (fixed order, deterministic) ----
    if (tid == 0) {
        __threadfence();
        int old = atomicAdd(&g_count, 1);
        s_isLast = (old == NBLK - 1);
    }
    __syncthreads();
    if (s_isLast && tid < 256) {
        __threadfence();
        // g_partial = 128 x 16 = 512 float4
        const float4* gp4 = reinterpret_cast<const float4*>(&g_partial[0][0]);
        float4 v = f4_add(gp4[tid], gp4[tid + 256]);
        v = f4_add(v, f4_shfl_xor(v, 4));
        v = f4_add(v, f4_shfl_xor(v, 8));
        v = f4_add(v, f4_shfl_xor(v, 16));
        if (lane < 4) red_smf[warp][lane] = v;
        __syncwarp();
    }
    __syncthreads();
    if (s_isLast) {
        if (tid < 4) {
            float4 t = red_smf[0][tid];
#pragma unroll
            for (int w = 1; w < 8; w++) t = f4_add(t, red_smf[w][tid]);
            const float invn = 1.0f / (float)NTOK;
            float s = 0.0f, pe;
            pe = t.x * invn; s += pe * logf(pe * (float)E_ + 1e-9f);
            pe = t.y * invn; s += pe * logf(pe * (float)E_ + 1e-9f);
            pe = t.z * invn; s += pe * logf(pe * (float)E_ + 1e-9f);
            pe = t.w * invn; s += pe * logf(pe * (float)E_ + 1e-9f);
            red_sterm[tid] = s;
        }
        __syncthreads();
        if (tid == 0) {
            out[(size_t)NTOK * TOPK * 2] = red_sterm[0] + red_sterm[1]
                                         + red_sterm[2] + red_sterm[3];
            g_count = 0;                 // reset for next graph replay
        }
    }
}

extern "C" void kernel_launch(void* const* d_in, const int* in_sizes, int n_in,
                              void* d_out, int out_size)
{
    (void)in_sizes; (void)n_in; (void)out_size;
    const float* x   = (const float*)d_in[0];
    const float* img = (const float*)d_in[1];
    const float* txt = (const float*)d_in[2];
    const float* aud = (const float*)d_in[3];
    const float* Wg  = (const float*)d_in[4];
    const float* bg  = (const float*)d_in[5];
    const float* Wi  = (const float*)d_in[6];
    const float* bi  = (const float*)d_in[7];
    const float* Wt  = (const float*)d_in[8];
    const float* bt  = (const float*)d_in[9];
    const float* Wa  = (const float*)d_in[10];
    const float* ba  = (const float*)d_in[11];
    float* out = (float*)d_out;

    cudaFuncSetAttribute(router_main, cudaFuncAttributeMaxDynamicSharedMemorySize, SMEMB);

    transpose_W<<<64, 256>>>(Wg, Wi, Wt, Wa);
    router_main<<<NBLK, NTHR, SMEMB>>>(x, img, txt, aud, bg, bi, bt, ba, out);
}

// round 13
// speedup vs baseline: 3.3481x; 1.2018x over previous
#include <cuda_runtime.h>
#include <cstdint>

// FlexMoERouter: logits[8192,16] = x*Wg + image*Wi + text*Wt + audio*Wa + biases
// -> softmax -> top4 (renorm) -> aux loss.
// Output (float32): [0,32768) idx as float, [32768,65536) probs, [65536] aux.

#define B_    4
#define S_    2048
#define H_    1024
#define E_    16
#define TOPK  4
#define NTOK  (B_ * S_)        // 8192
#define TPB   64               // tokens per block
#define NTHR  512
#define NWRP  16               // 16 warps = 16 k-classes, 1 token-group
#define NBLK  (NTOK / TPB)     // 128 blocks (one per SM)
#define KC    128              // k floats per stage
#define NSTG  32               // 4 modalities x 8 k-chunks
#define NBUF  4
#define RSTR  132              // smem row stride (floats): 33x16B granules (odd)
#define RPB   (TPB + E_)       // 80 rows per buffer (64 x + 16 W)

#define BUF(b)  ((b) * (RPB * RSTR))
#define SMEMF   (NBUF * RPB * RSTR)          // 42240 floats
#define SMEMB   (SMEMF * 4)                  // 168960 bytes

__device__ float g_Wt[4][E_][H_];       // transposed weights: g_Wt[m][e][k]
__device__ float g_partial[NBLK][E_];   // per-block sum of router_probs per expert
__device__ int   g_count;               // zero-init; self-resets each launch

__device__ __forceinline__ void fma2(unsigned long long& acc,
                                     unsigned long long a, unsigned long long b)
{
    asm("fma.rn.f32x2 %0, %1, %2, %0;" : "+l"(acc) : "l"(a), "l"(b));
}
__device__ __forceinline__ float fma2_lo(unsigned long long v) {
    return __uint_as_float((unsigned)(v & 0xffffffffull));
}
__device__ __forceinline__ float fma2_hi(unsigned long long v) {
    return __uint_as_float((unsigned)(v >> 32));
}
__device__ __forceinline__ void cp16(uint32_t dst_s, const float* src)
{
    asm volatile("cp.async.cg.shared.global [%0], [%1], 16;" :: "r"(dst_s), "l"(src));
}
__device__ __forceinline__ void cp_commit() { asm volatile("cp.async.commit_group;"); }
__device__ __forceinline__ void cp_wait2()  { asm volatile("cp.async.wait_group 2;"); }
__device__ __forceinline__ void cp_wait0()  { asm volatile("cp.async.wait_group 0;"); }

__device__ __forceinline__ float4 f4_add(float4 a, float4 b) {
    return make_float4(a.x + b.x, a.y + b.y, a.z + b.z, a.w + b.w);
}
__device__ __forceinline__ float4 f4_shfl_xor(float4 v, int m) {
    float4 r;
    r.x = __shfl_xor_sync(0xffffffffu, v.x, m);
    r.y = __shfl_xor_sync(0xffffffffu, v.y, m);
    r.z = __shfl_xor_sync(0xffffffffu, v.z, m);
    r.w = __shfl_xor_sync(0xffffffffu, v.w, m);
    return r;
}

// Pre-kernel: transpose W[1024][16] -> g_Wt[m][16][1024].
__global__ void transpose_W(const float* __restrict__ Wg, const float* __restrict__ Wi,
                            const float* __restrict__ Wt, const float* __restrict__ Wa)
{
    const float* Ws[4] = {Wg, Wi, Wt, Wa};
    const int idx = blockIdx.x * 256 + threadIdx.x;   // 0..16383
    const int m = idx >> 12;
    const int r = idx & 4095;
    const int k = r >> 2;
    const int ec = r & 3;
    float4 v = reinterpret_cast<const float4*>(Ws[m])[r];
    g_Wt[m][ec * 4 + 0][k] = v.x;
    g_Wt[m][ec * 4 + 1][k] = v.y;
    g_Wt[m][ec * 4 + 2][k] = v.z;
    g_Wt[m][ec * 4 + 3][k] = v.w;
}

__global__ __launch_bounds__(NTHR, 1)
void router_main(const float* __restrict__ x,   const float* __restrict__ img,
                 const float* __restrict__ txt, const float* __restrict__ aud,
                 const float* __restrict__ bg,  const float* __restrict__ bi,
                 const float* __restrict__ bt,  const float* __restrict__ ba,
                 float* __restrict__ out)
{
    extern __shared__ float sm[];
    __shared__ float  sl[TPB][E_];       // logits (bias included)
    __shared__ float  bsum[E_];
    __shared__ float  wpart[2][E_];
    __shared__ float4 red_smf[8][4];
    __shared__ float  red_sterm[4];
    __shared__ int    s_isLast;

    const int tid  = threadIdx.x;
    const int lane = tid & 31;
    const int warp = tid >> 5;             // 0..15 = k-class (granule g % 16 == warp)
    const int tokB0 = blockIdx.x * TPB;

    const float* xs_[4] = {x, img, txt, aud};
    const uint32_t smem_base = (uint32_t)__cvta_generic_to_shared(sm);

    if (tid < E_) bsum[tid] = bg[tid] + bi[tid] + bt[tid] + ba[tid];

    // Two tokens per thread: lane and lane+32. acc over (even-k, odd-k) pairs.
    unsigned long long acc0[E_], acc1[E_];
#pragma unroll
    for (int e = 0; e < E_; e++) { acc0[e] = 0ull; acc1[e] = 0ull; }

    // ---- async stage issue: x 64 rows x 128k (32KB) + W 16 rows x 128k (8KB) ----
    auto issue = [&](int s) {
        const int m  = s >> 3;
        const int kc = (s & 7) * KC;
        const int b  = s & (NBUF - 1);
        const uint32_t bd = smem_base + BUF(b) * 4;
        const float* xsrc = xs_[m] + (size_t)tokB0 * H_ + kc;
#pragma unroll
        for (int j = 0; j < 4; j++) {
            const int idx = tid + NTHR * j;        // 0..2047
            const int row = idx >> 5;
            const int g   = idx & 31;
            cp16(bd + (uint32_t)(row * RSTR + g * 4) * 4, xsrc + row * H_ + g * 4);
        }
        {
            const float* wsrc = &g_Wt[m][0][kc];
            const int row = tid >> 5;              // 0..15
            const int g   = tid & 31;
            cp16(bd + (uint32_t)((TPB + row) * RSTR + g * 4) * 4, wsrc + row * H_ + g * 4);
        }
        cp_commit();
    };

    issue(0); issue(1); issue(2);
#pragma unroll 1
    for (int s = 0; s < NSTG; s++) {
        if (s >= NSTG - 3) cp_wait0(); else cp_wait2();
        __syncthreads();                  // stage s visible; buf (s-1)%4 drained by all
        if (s + 3 < NSTG) issue(s + 3);

        const int b = s & (NBUF - 1);
        const float* xb = sm + BUF(b);
        const float* wb = xb + TPB * RSTR;
        const ulonglong2* xr0 = reinterpret_cast<const ulonglong2*>(xb + lane * RSTR);
        const ulonglong2* xr1 = reinterpret_cast<const ulonglong2*>(xb + (lane + 32) * RSTR);

#pragma unroll
        for (int i = 0; i < 2; i++) {
            const int o = warp + 16 * i;           // this warp's granule in stage
            const ulonglong2 xv0 = xr0[o];
            const ulonglong2 xv1 = xr1[o];
#pragma unroll
            for (int e = 0; e < E_; e++) {
                const ulonglong2 wv =
                    reinterpret_cast<const ulonglong2*>(wb + e * RSTR)[o];  // warp-uniform
                fma2(acc0[e], xv0.x, wv.x);
                fma2(acc0[e], xv0.y, wv.y);
                fma2(acc1[e], xv1.x, wv.x);
                fma2(acc1[e], xv1.y, wv.y);
            }
        }
    }
    __syncthreads();                       // all compute done; stage bufs reusable

    // ---- cross-warp (k) reduction via smem: red[wk][tok][e] (16*64*16 = 64KB) ----
    float* red = sm;
    {
        float4* dst0 = reinterpret_cast<float4*>(red + warp * (TPB * E_) + lane * E_);
        float4* dst1 = reinterpret_cast<float4*>(red + warp * (TPB * E_) + (lane + 32) * E_);
#pragma unroll
        for (int q = 0; q < 4; q++) {
            dst0[q] = make_float4(
                fma2_lo(acc0[q * 4 + 0]) + fma2_hi(acc0[q * 4 + 0]),
                fma2_lo(acc0[q * 4 + 1]) + fma2_hi(acc0[q * 4 + 1]),
                fma2_lo(acc0[q * 4 + 2]) + fma2_hi(acc0[q * 4 + 2]),
                fma2_lo(acc0[q * 4 + 3]) + fma2_hi(acc0[q * 4 + 3]));
            dst1[q] = make_float4(
                fma2_lo(acc1[q * 4 + 0]) + fma2_hi(acc1[q * 4 + 0]),
                fma2_lo(acc1[q * 4 + 1]) + fma2_hi(acc1[q * 4 + 1]),
                fma2_lo(acc1[q * 4 + 2]) + fma2_hi(acc1[q * 4 + 2]),
                fma2_lo(acc1[q * 4 + 3]) + fma2_hi(acc1[q * 4 + 3]));
        }
    }
    __syncthreads();

    if (tid < 256) {   // each sums 16 k-partials for (token, expert-quad)
        const int t = tid >> 2;
        const int q = tid & 3;
        float4 s4 = make_float4(0.f, 0.f, 0.f, 0.f);
#pragma unroll
        for (int w = 0; w < NWRP; w++)
            s4 = f4_add(s4, reinterpret_cast<const float4*>(
                                red + w * (TPB * E_) + t * E_ + q * 4)[0]);
        const float4 bq = reinterpret_cast<const float4*>(bsum)[q];
        reinterpret_cast<float4*>(&sl[t][q * 4])[0] = f4_add(s4, bq);
    }
    __syncthreads();

    // ---- epilogue: threads 0..63, one token each ----
    if (tid < TPB) {
        const int g = blockIdx.x * TPB + tid;
        float p[E_], q[E_];
        float mx = -1e30f;
#pragma unroll
        for (int e = 0; e < E_; e++) {
            float l = sl[tid][e];
            p[e] = l;
            mx = fmaxf(mx, l);
        }
        float ssum = 0.0f;
#pragma unroll
        for (int e = 0; e < E_; e++) { p[e] = expf(p[e] - mx); ssum += p[e]; }
        const float inv = 1.0f / ssum;
#pragma unroll
        for (int e = 0; e < E_; e++) { p[e] *= inv; q[e] = p[e]; }

        float tp[TOPK]; int ti[TOPK]; float tsum = 0.0f;
#pragma unroll
        for (int j = 0; j < TOPK; j++) {
            float best = -1.0f; int bidx = 0;
#pragma unroll
            for (int e = 0; e < E_; e++)
                if (p[e] > best) { best = p[e]; bidx = e; }
            tp[j] = best; ti[j] = bidx; tsum += best;
            p[bidx] = -2.0f;
        }
        const float tinv = 1.0f / tsum;
        float4* oi = reinterpret_cast<float4*>(out + (size_t)g * TOPK);
        float4* op = reinterpret_cast<float4*>(out + (size_t)NTOK * TOPK + (size_t)g * TOPK);
        *oi = make_float4((float)ti[0], (float)ti[1], (float)ti[2], (float)ti[3]);
        *op = make_float4(tp[0] * tinv, tp[1] * tinv, tp[2] * tinv, tp[3] * tinv);

        // per-expert prob sums (warp 0: tokens 0-31, warp 1: 32-63)
#pragma unroll
        for (int e = 0; e < E_; e++) {
            float v = q[e];
            v += __shfl_xor_sync(0xffffffffu, v, 16);
            v += __shfl_xor_sync(0xffffffffu, v, 8);
            v += __shfl_xor_sync(0xffffffffu, v, 4);
            v += __shfl_xor_sync(0xffffffffu, v, 2);
            v += __shfl_xor_sync(0xffffffffu, v, 1);
            if (lane == 0) wpart[warp][e] = v;
        }
    }
    __syncthreads();
    if (tid < E_)
        g_partial[blockIdx.x][tid] = wpart[0][tid] + wpart[1][tid];
    __syncthreads();

    // ---- last block reduces g_partial -> aux loss (fixed order, deterministic) ----
    if (tid == 0) {
        __threadfence();
        int old = atomicAdd(&g_count, 1);
        s_isLast = (old == NBLK - 1);
    }
    __syncthreads();
    if (s_isLast && tid < 256) {
        __threadfence();
        // g_partial = 128 x 16 = 512 float4
        const float4* gp4 = reinterpret_cast<const float4*>(&g_partial[0][0]);
        float4 v = f4_add(gp4[tid], gp4[tid + 256]);
        v = f4_add(v, f4_shfl_xor(v, 4));
        v = f4_add(v, f4_shfl_xor(v, 8));
        v = f4_add(v, f4_shfl_xor(v, 16));
        if (lane < 4) red_smf[warp][lane] = v;
        __syncwarp();
    }
    __syncthreads();
    if (s_isLast) {
        if (tid < 4) {
            float4 t = red_smf[0][tid];
#pragma unroll
            for (int w = 1; w < 8; w++) t = f4_add(t, red_smf[w][tid]);
            const float invn = 1.0f / (float)NTOK;
            float s = 0.0f, pe;
            pe = t.x * invn; s += pe * logf(pe * (float)E_ + 1e-9f);
            pe = t.y * invn; s += pe * logf(pe * (float)E_ + 1e-9f);
            pe = t.z * invn; s += pe * logf(pe * (float)E_ + 1e-9f);
            pe = t.w * invn; s += pe * logf(pe * (float)E_ + 1e-9f);
            red_sterm[tid] = s;
        }
        __syncthreads();
        if (tid == 0) {
            out[(size_t)NTOK * TOPK * 2] = red_sterm[0] + red_sterm[1]
                                         + red_sterm[2] + red_sterm[3];
            g_count = 0;                 // reset for next graph replay
        }
    }
}

extern "C" void kernel_launch(void* const* d_in, const int* in_sizes, int n_in,
                              void* d_out, int out_size)
{
    (void)in_sizes; (void)n_in; (void)out_size;
    const float* x   = (const float*)d_in[0];
    const float* img = (const float*)d_in[1];
    const float* txt = (const float*)d_in[2];
    const float* aud = (const float*)d_in[3];
    const float* Wg  = (const float*)d_in[4];
    const float* bg  = (const float*)d_in[5];
    const float* Wi  = (const float*)d_in[6];
    const float* bi  = (const float*)d_in[7];
    const float* Wt  = (const float*)d_in[8];
    const float* bt  = (const float*)d_in[9];
    const float* Wa  = (const float*)d_in[10];
    const float* ba  = (const float*)d_in[11];
    float* out = (float*)d_out;

    cudaFuncSetAttribute(router_main, cudaFuncAttributeMaxDynamicSharedMemorySize, SMEMB);

    transpose_W<<<64, 256>>>(Wg, Wi, Wt, Wa);
    router_main<<<NBLK, NTHR, SMEMB>>>(x, img, txt, aud, bg, bi, bt, ba, out);
}